// round 2
// baseline (speedup 1.0000x reference)
#include <cuda_runtime.h>
#include <cstdint>

// Problem constants (fixed shapes for this problem)
#define T_STEPS 512
#define BATCH   64
#define N_IN    512
#define HID     1024

// LSNN parameters
#define DT_TAU_MEM   0.1f       // DT * TAU_MEM_INV
#define DT_TAU_SYN   0.2f       // DT * TAU_SYN_INV
#define DT_TAU_ADAPT 1.25e-6f   // DT * TAU_ADAPT_INV
#define VTH          1.0f
#define BETA         1.8f

// ---------------------------------------------------------------------------
// Scratch (static device globals; no allocation allowed)
// ---------------------------------------------------------------------------
__device__ float g_curin[(size_t)T_STEPS * BATCH * HID];   // x @ w_in^T, [T,B,H]
__device__ float g_wrecT[(size_t)HID * HID];               // w_rec^T  [h' , h]
__device__ float g_winT [(size_t)N_IN * HID];              // w_in^T   [k  , h]

// ---------------------------------------------------------------------------
// Tiled transposes writing directly to device symbols (no cudaGetSymbolAddress
// in the launch path).
// ---------------------------------------------------------------------------
__device__ __forceinline__ void transpose_impl(const float* __restrict__ in,
                                               float* __restrict__ out,
                                               int rows, int cols)
{
    __shared__ float tile[32][33];
    int c = blockIdx.x * 32 + threadIdx.x;
    int r = blockIdx.y * 32 + threadIdx.y;
#pragma unroll
    for (int j = 0; j < 32; j += 8) {
        if (r + j < rows && c < cols)
            tile[threadIdx.y + j][threadIdx.x] = in[(size_t)(r + j) * cols + c];
    }
    __syncthreads();
    int c2 = blockIdx.y * 32 + threadIdx.x;   // index into 'rows' dim of input
    int r2 = blockIdx.x * 32 + threadIdx.y;   // index into 'cols' dim of input
#pragma unroll
    for (int j = 0; j < 32; j += 8) {
        if (r2 + j < cols && c2 < rows)
            out[(size_t)(r2 + j) * rows + c2] = tile[threadIdx.x][threadIdx.y + j];
    }
}

__global__ void transpose_wrec_kernel(const float* __restrict__ w_rec)
{
    transpose_impl(w_rec, g_wrecT, HID, HID);
}

__global__ void transpose_win_kernel(const float* __restrict__ w_in)
{
    transpose_impl(w_in, g_winT, HID, N_IN);
}

// ---------------------------------------------------------------------------
// SGEMM (NN): C[M,N] = A[M,K] * B[K,N]
// A = x   [T*B, N_IN] row-major (as given)
// B = g_winT [N_IN, HID]
// C = g_curin [T*B, HID]
// 128x128 tile, BK=8, 256 threads, 8x8 microtile. Sequential-k accumulation.
// ---------------------------------------------------------------------------
#define BM 128
#define BN 128
#define BK 8
#define TM 8
#define TN 8

__global__ void __launch_bounds__(256, 2)
sgemm_nn_kernel(const float* __restrict__ A)
{
    const int K = N_IN;
    const int N = HID;

    __shared__ float As[BK][BM];
    __shared__ float Bs[BK][BN];

    const int bm = blockIdx.y * BM;
    const int bn = blockIdx.x * BN;
    const int tid = threadIdx.x;

    // A tile load mapping: 128 rows x 8 cols, 4 floats/thread (float4)
    const int arow = tid >> 1;
    const int ak   = (tid & 1) * 4;
    // B tile load mapping: 8 rows x 128 cols, 4 floats/thread (float4)
    const int brow = tid >> 5;
    const int bcol = (tid & 31) * 4;

    const int tx = (tid & 15) * TN;
    const int ty = (tid >> 4) * TM;

    float acc[TM][TN];
#pragma unroll
    for (int m = 0; m < TM; m++)
#pragma unroll
        for (int n = 0; n < TN; n++) acc[m][n] = 0.0f;

    const float* Aptr = A + (size_t)(bm + arow) * K + ak;
    const float* Bptr = g_winT + (size_t)brow * N + bn + bcol;

    for (int k0 = 0; k0 < K; k0 += BK) {
        float4 av = *(const float4*)Aptr;  Aptr += BK;
        float4 bv = *(const float4*)Bptr;  Bptr += (size_t)BK * N;

        As[ak + 0][arow] = av.x;
        As[ak + 1][arow] = av.y;
        As[ak + 2][arow] = av.z;
        As[ak + 3][arow] = av.w;
        *(float4*)&Bs[brow][bcol] = bv;
        __syncthreads();

#pragma unroll
        for (int kk = 0; kk < BK; kk++) {
            float ar[TM], br[TN];
#pragma unroll
            for (int m = 0; m < TM; m++) ar[m] = As[kk][ty + m];
#pragma unroll
            for (int n = 0; n < TN; n++) br[n] = Bs[kk][tx + n];
#pragma unroll
            for (int m = 0; m < TM; m++)
#pragma unroll
                for (int n = 0; n < TN; n++)
                    acc[m][n] += ar[m] * br[n];
        }
        __syncthreads();
    }

    float* Cbase = g_curin + (size_t)(bm + ty) * N + bn + tx;
#pragma unroll
    for (int m = 0; m < TM; m++) {
        float* crow = Cbase + (size_t)m * N;
#pragma unroll
        for (int n = 0; n < TN; n += 4) {
            float4 v = make_float4(acc[m][n], acc[m][n + 1], acc[m][n + 2], acc[m][n + 3]);
            *(float4*)(crow + n) = v;
        }
    }
}

// ---------------------------------------------------------------------------
// LSNN scan: one CTA per batch element, 1024 threads = 1 neuron each.
// All state in registers; previous-step spike indices compacted into smem
// (deterministic ascending order) so the recurrent matvec is a sparse sum
// of rows of w_rec^T.
// ---------------------------------------------------------------------------
__global__ void __launch_bounds__(HID, 1)
lsnn_scan_kernel(float* __restrict__ out)
{
    const int h     = threadIdx.x;
    const int batch = blockIdx.x;
    const int lane  = h & 31;
    const int wid   = h >> 5;

    __shared__ int   s_list[HID];
    __shared__ int   s_warpcnt[32];
    __shared__ int   s_warpbase[32];
    __shared__ int   s_cnt;

    float v   = 0.0f;   // membrane
    float cur = 0.0f;   // synaptic current i
    float bth = VTH;    // adaptive threshold b
    float zlast = 0.0f;
    int cnt = 0;        // spikes in s_list (previous step)

    const float* cin  = g_curin + (size_t)batch * HID + h;
    float*       outp = out     + (size_t)batch * HID + h;
    const size_t strideT = (size_t)BATCH * HID;

    if (h == 0) s_cnt = 0;
    __syncthreads();

    for (int t = 0; t < T_STEPS; t++) {
        float gin = __ldg(cin + (size_t)t * strideT);

        // recurrent input: sum over previous step's spikes (ascending h')
        float rec = 0.0f;
        int k = 0;
        for (; k + 4 <= cnt; k += 4) {
            int i0 = s_list[k], i1 = s_list[k + 1], i2 = s_list[k + 2], i3 = s_list[k + 3];
            float w0 = g_wrecT[(size_t)i0 * HID + h];
            float w1 = g_wrecT[(size_t)i1 * HID + h];
            float w2 = g_wrecT[(size_t)i2 * HID + h];
            float w3 = g_wrecT[(size_t)i3 * HID + h];
            rec += w0; rec += w1; rec += w2; rec += w3;
        }
        for (; k < cnt; k++) rec += g_wrecT[(size_t)s_list[k] * HID + h];

        // elementwise dynamics (mirrors reference expression order)
        float vd   = v + DT_TAU_MEM * (cur - v);          // v + 0.1*(-v + i)
        float idec = cur - DT_TAU_SYN * cur;              // 0.8*i
        float bd   = bth + DT_TAU_ADAPT * (VTH - bth);
        bool  z    = (vd - bd) > 0.0f;
        float zf   = z ? 1.0f : 0.0f;

        v   = z ? 0.0f : vd;
        bth = bd + (z ? BETA : 0.0f);
        cur = (idec + gin) + rec;                          // uses PREVIOUS z's rec
        zlast = zf;

        outp[(size_t)t * strideT] = zf;

        // --- rebuild spike list for next step (deterministic compaction) ---
        unsigned m = __ballot_sync(0xffffffffu, z);
        if (lane == 0) s_warpcnt[wid] = __popc(m);
        __syncthreads();   // (A) old list fully consumed; warp counts visible

        if (wid == 0) {
            int c = s_warpcnt[lane];
            int inc = c;
#pragma unroll
            for (int off = 1; off < 32; off *= 2) {
                int nbr = __shfl_up_sync(0xffffffffu, inc, off);
                if (lane >= off) inc += nbr;
            }
            s_warpbase[lane] = inc - c;   // exclusive prefix
            if (lane == 31) s_cnt = inc;
        }
        __syncthreads();   // (B) bases + total ready

        if (z) {
            int pos = s_warpbase[wid] + __popc(m & ((1u << lane) - 1u));
            s_list[pos] = h;
        }
        cnt = s_cnt;
        __syncthreads();   // (C) list ready for next iteration
    }

    // final states: (zf, vf, if, bf) appended after outs [T,B,H]
    const size_t BH = (size_t)BATCH * HID;
    float* fbase = out + (size_t)T_STEPS * BH + (size_t)batch * HID + h;
    fbase[0 * BH] = zlast;
    fbase[1 * BH] = v;
    fbase[2 * BH] = cur;
    fbase[3 * BH] = bth;
}

// ---------------------------------------------------------------------------
// Launch
// ---------------------------------------------------------------------------
extern "C" void kernel_launch(void* const* d_in, const int* in_sizes, int n_in,
                              void* d_out, int out_size)
{
    const float* x     = (const float*)d_in[0];  // [T, B, N_IN]
    const float* w_in  = (const float*)d_in[1];  // [H, N_IN]
    const float* w_rec = (const float*)d_in[2];  // [H, H]
    float* out = (float*)d_out;

    // 1) transposes: w_rec -> g_wrecT, w_in -> g_winT (write to symbols directly)
    {
        dim3 blk(32, 8);
        dim3 g1(HID / 32, HID / 32);
        transpose_wrec_kernel<<<g1, blk>>>(w_rec);
        dim3 g2(N_IN / 32, HID / 32);
        transpose_win_kernel<<<g2, blk>>>(w_in);
    }

    // 2) input GEMM: g_curin = x @ w_in^T   ([T*B, N_IN] x [N_IN, H])
    {
        dim3 grid(HID / BN, (T_STEPS * BATCH) / BM);
        sgemm_nn_kernel<<<grid, 256>>>(x);
    }

    // 3) recurrent scan (one CTA per batch element)
    {
        lsnn_scan_kernel<<<BATCH, HID>>>(out);
    }
}

// round 3
// speedup vs baseline: 1.0827x; 1.0827x over previous
#include <cuda_runtime.h>
#include <cstdint>

// Problem constants (fixed shapes for this problem)
#define T_STEPS 512
#define BATCH   64
#define N_IN    512
#define HID     1024

// LSNN parameters
#define DT_TAU_MEM   0.1f
#define DT_TAU_SYN   0.2f
#define DT_TAU_ADAPT 1.25e-6f
#define VTH          1.0f
#define BETA         1.8f

// ---------------------------------------------------------------------------
// Scratch (static device globals; no allocation allowed)
// ---------------------------------------------------------------------------
__device__ float g_curin[(size_t)T_STEPS * BATCH * HID];   // x @ w_in^T, [T,B,H]
__device__ float g_wrecT[(size_t)HID * HID];               // w_rec^T  [h' , h]
__device__ float g_winT [(size_t)N_IN * HID];              // w_in^T   [k  , h]

// ---------------------------------------------------------------------------
// Packed fp32x2 helpers (Blackwell FFMA2 — 2 fp32 FMAs per issue, exact fp32
// rounding per lane, bitwise identical to scalar FFMA)
// ---------------------------------------------------------------------------
__device__ __forceinline__ unsigned long long pack_f32x2(float lo, float hi)
{
    unsigned long long r;
    asm("mov.b64 %0, {%1, %2};" : "=l"(r) : "r"(__float_as_uint(lo)), "r"(__float_as_uint(hi)));
    return r;
}
__device__ __forceinline__ void fma_f32x2(unsigned long long& d,
                                          unsigned long long a, unsigned long long b)
{
    asm("fma.rn.f32x2 %0, %1, %2, %0;" : "+l"(d) : "l"(a), "l"(b));
}
__device__ __forceinline__ float2 unpack_f32x2(unsigned long long p)
{
    unsigned int lo, hi;
    asm("mov.b64 {%0, %1}, %2;" : "=r"(lo), "=r"(hi) : "l"(p));
    return make_float2(__uint_as_float(lo), __uint_as_float(hi));
}

// ---------------------------------------------------------------------------
// Tiled transposes writing directly to device symbols
// ---------------------------------------------------------------------------
__device__ __forceinline__ void transpose_impl(const float* __restrict__ in,
                                               float* __restrict__ out,
                                               int rows, int cols)
{
    __shared__ float tile[32][33];
    int c = blockIdx.x * 32 + threadIdx.x;
    int r = blockIdx.y * 32 + threadIdx.y;
#pragma unroll
    for (int j = 0; j < 32; j += 8) {
        if (r + j < rows && c < cols)
            tile[threadIdx.y + j][threadIdx.x] = in[(size_t)(r + j) * cols + c];
    }
    __syncthreads();
    int c2 = blockIdx.y * 32 + threadIdx.x;
    int r2 = blockIdx.x * 32 + threadIdx.y;
#pragma unroll
    for (int j = 0; j < 32; j += 8) {
        if (r2 + j < cols && c2 < rows)
            out[(size_t)(r2 + j) * rows + c2] = tile[threadIdx.x][threadIdx.y + j];
    }
}

__global__ void transpose_wrec_kernel(const float* __restrict__ w_rec)
{
    transpose_impl(w_rec, g_wrecT, HID, HID);
}

__global__ void transpose_win_kernel(const float* __restrict__ w_in)
{
    transpose_impl(w_in, g_winT, HID, N_IN);
}

// ---------------------------------------------------------------------------
// SGEMM (NN): g_curin[T*B, HID] = x[T*B, N_IN] * g_winT[N_IN, HID]
// 128x128 tile, BK=8, 256 threads, 8x8 microtile.
// Double-buffered smem + packed f32x2 FMAs. Sequential-k accumulation
// (bitwise identical to the scalar version).
// ---------------------------------------------------------------------------
#define BM 128
#define BN 128
#define BK 8
#define TM 8
#define TN 8

__global__ void __launch_bounds__(256, 2)
sgemm_nn_kernel(const float* __restrict__ A)
{
    const int K = N_IN;
    const int N = HID;

    __shared__ float As[2][BK][BM];
    __shared__ float Bs[2][BK][BN];

    const int bm = blockIdx.y * BM;
    const int bn = blockIdx.x * BN;
    const int tid = threadIdx.x;

    const int arow = tid >> 1;
    const int ak   = (tid & 1) * 4;
    const int brow = tid >> 5;
    const int bcol = (tid & 31) * 4;

    const int tx = (tid & 15) * TN;
    const int ty = (tid >> 4) * TM;

    unsigned long long acc2[TM][TN / 2];
#pragma unroll
    for (int m = 0; m < TM; m++)
#pragma unroll
        for (int j = 0; j < TN / 2; j++) acc2[m][j] = 0ull;   // {0.f, 0.f}

    const float* Aptr = A + (size_t)(bm + arow) * K + ak;
    const float* Bptr = g_winT + (size_t)brow * N + bn + bcol;

    // prologue: stage tile 0
    float4 av = *(const float4*)Aptr;  Aptr += BK;
    float4 bv = *(const float4*)Bptr;  Bptr += (size_t)BK * N;
    As[0][ak + 0][arow] = av.x;
    As[0][ak + 1][arow] = av.y;
    As[0][ak + 2][arow] = av.z;
    As[0][ak + 3][arow] = av.w;
    *(float4*)&Bs[0][brow][bcol] = bv;
    __syncthreads();

    const int NIT = K / BK;   // 64
    for (int k0 = 0; k0 < NIT; k0++) {
        const int cur = k0 & 1;

        if (k0 + 1 < NIT) {
            av = *(const float4*)Aptr;  Aptr += BK;
            bv = *(const float4*)Bptr;  Bptr += (size_t)BK * N;
        }

#pragma unroll
        for (int kk = 0; kk < BK; kk++) {
            unsigned long long bb[TN / 2];
#pragma unroll
            for (int j = 0; j < TN / 2; j++) {
                float2 t = *(const float2*)&Bs[cur][kk][tx + 2 * j];
                bb[j] = pack_f32x2(t.x, t.y);
            }
#pragma unroll
            for (int m = 0; m < TM; m++) {
                float a = As[cur][kk][ty + m];
                unsigned long long a2 = pack_f32x2(a, a);
#pragma unroll
                for (int j = 0; j < TN / 2; j++)
                    fma_f32x2(acc2[m][j], a2, bb[j]);
            }
        }

        if (k0 + 1 < NIT) {
            const int nxt = cur ^ 1;
            As[nxt][ak + 0][arow] = av.x;
            As[nxt][ak + 1][arow] = av.y;
            As[nxt][ak + 2][arow] = av.z;
            As[nxt][ak + 3][arow] = av.w;
            *(float4*)&Bs[nxt][brow][bcol] = bv;
            __syncthreads();
        }
    }

    float* Cbase = g_curin + (size_t)(bm + ty) * N + bn + tx;
#pragma unroll
    for (int m = 0; m < TM; m++) {
        float* crow = Cbase + (size_t)m * N;
#pragma unroll
        for (int j = 0; j < TN / 2; j += 2) {
            float2 v0 = unpack_f32x2(acc2[m][j]);
            float2 v1 = unpack_f32x2(acc2[m][j + 1]);
            float4 v = make_float4(v0.x, v0.y, v1.x, v1.y);
            *(float4*)(crow + 2 * j) = v;
        }
    }
}

// ---------------------------------------------------------------------------
// LSNN scan: one CTA per batch element, 1024 threads = 1 neuron each.
// - state in registers
// - double-buffered spike list (2 barriers/step instead of 3)
// - redundant per-warp shuffle scan of warp counts (no warp-0 serialization)
// - gin prefetched one full step ahead
// ---------------------------------------------------------------------------
__global__ void __launch_bounds__(HID, 1)
lsnn_scan_kernel(float* __restrict__ out)
{
    const int h     = threadIdx.x;
    const int batch = blockIdx.x;
    const int lane  = h & 31;
    const int wid   = h >> 5;
    const unsigned FULL = 0xffffffffu;

    __shared__ int s_list[2][HID];
    __shared__ int s_warpcnt[32];

    float v   = 0.0f;
    float cur = 0.0f;
    float bth = VTH;
    float zlast = 0.0f;
    int cnt = 0;
    int buf = 0;

    const float* cin  = g_curin + (size_t)batch * HID + h;
    float*       outp = out     + (size_t)batch * HID + h;
    const size_t strideT = (size_t)BATCH * HID;

    float gin = __ldg(cin);   // t = 0

    for (int t = 0; t < T_STEPS; t++) {
        // prefetch next step's feedforward current (latency hidden by this step)
        float gin_next = (t + 1 < T_STEPS) ? __ldg(cin + (size_t)(t + 1) * strideT) : 0.0f;

        // recurrent input: sum over previous step's spikes (ascending h')
        float rec = 0.0f;
        {
            const int* lst = s_list[buf];
            int k = 0;
            for (; k + 4 <= cnt; k += 4) {
                int i0 = lst[k], i1 = lst[k + 1], i2 = lst[k + 2], i3 = lst[k + 3];
                float w0 = g_wrecT[(size_t)i0 * HID + h];
                float w1 = g_wrecT[(size_t)i1 * HID + h];
                float w2 = g_wrecT[(size_t)i2 * HID + h];
                float w3 = g_wrecT[(size_t)i3 * HID + h];
                rec += w0; rec += w1; rec += w2; rec += w3;
            }
            for (; k < cnt; k++) rec += g_wrecT[(size_t)lst[k] * HID + h];
        }

        // elementwise dynamics (mirrors reference expression order)
        float vd   = v + DT_TAU_MEM * (cur - v);
        float idec = cur - DT_TAU_SYN * cur;
        float bd   = bth + DT_TAU_ADAPT * (VTH - bth);
        bool  z    = (vd - bd) > 0.0f;
        float zf   = z ? 1.0f : 0.0f;

        v   = z ? 0.0f : vd;
        bth = bd + (z ? BETA : 0.0f);
        cur = (idec + gin) + rec;
        zlast = zf;

        outp[(size_t)t * strideT] = zf;

        // --- rebuild spike list (double-buffered, 2 barriers) ---
        unsigned m = __ballot_sync(FULL, z);
        if (lane == 0) s_warpcnt[wid] = __popc(m);
        __syncthreads();   // (X) counts visible; old-list reads complete

        // every warp redundantly scans the 32 warp counts
        int c   = s_warpcnt[lane];
        int inc = c;
#pragma unroll
        for (int off = 1; off < 32; off *= 2) {
            int nbr = __shfl_up_sync(FULL, inc, off);
            if (lane >= off) inc += nbr;
        }
        int total   = __shfl_sync(FULL, inc, 31);
        int mybase  = __shfl_sync(FULL, inc, wid) - __shfl_sync(FULL, c, wid);

        const int nbuf = buf ^ 1;
        if (z) {
            int pos = mybase + __popc(m & ((1u << lane) - 1u));
            s_list[nbuf][pos] = h;
        }
        cnt = total;
        buf = nbuf;
        __syncthreads();   // (Y) new list ready

        gin = gin_next;
    }

    // final states: (zf, vf, if, bf) appended after outs [T,B,H]
    const size_t BH = (size_t)BATCH * HID;
    float* fbase = out + (size_t)T_STEPS * BH + (size_t)batch * HID + h;
    fbase[0 * BH] = zlast;
    fbase[1 * BH] = v;
    fbase[2 * BH] = cur;
    fbase[3 * BH] = bth;
}

// ---------------------------------------------------------------------------
// Launch
// ---------------------------------------------------------------------------
extern "C" void kernel_launch(void* const* d_in, const int* in_sizes, int n_in,
                              void* d_out, int out_size)
{
    const float* x     = (const float*)d_in[0];  // [T, B, N_IN]
    const float* w_in  = (const float*)d_in[1];  // [H, N_IN]
    const float* w_rec = (const float*)d_in[2];  // [H, H]
    float* out = (float*)d_out;

    {
        dim3 blk(32, 8);
        dim3 g2(N_IN / 32, HID / 32);
        transpose_win_kernel<<<g2, blk>>>(w_in);
        dim3 g1(HID / 32, HID / 32);
        transpose_wrec_kernel<<<g1, blk>>>(w_rec);
    }

    {
        dim3 grid(HID / BN, (T_STEPS * BATCH) / BM);
        sgemm_nn_kernel<<<grid, 256>>>(x);
    }

    {
        lsnn_scan_kernel<<<BATCH, HID>>>(out);
    }
}